// round 9
// baseline (speedup 1.0000x reference)
#include <cuda_runtime.h>

// Grouper: FPS (B=8, N=8192 -> S=2048) + KNN(K=32) grouping.
// Output layout: [neighborhood (B,S,K,3) | centers (B,S,3)] flattened.
//
// All distance math is scalar __fadd_rn/__fmul_rn (no FMA contraction, no
// packed f32x2 — R5 showed the packed path is NOT bit-identical), in the
// reference's ((dx^2+dy^2)+dz^2) evaluation order. All selections use 64-bit
// keys reproducing JAX first-occurrence (lowest-index) tie-breaking, over
// GLOBAL point indices, so the cluster split cannot change any selection.

#define BB 8
#define NN 8192
#define SS 2048
#define KK 32

#define FPS_T 256
#define HALF  (NN / 2)        // 4096 points per FPS CTA (cluster of 2)
#define FPP   (HALF / FPS_T)  // 16 points per thread
#define FW    (FPS_T / 32)    // 8 warps

#define KNN_T 256
#define KW    (KNN_T / 32)    // 8 warps
#define KPT   32              // points per thread (NN / KNN_T)

typedef unsigned long long ull;

// Scratch: centers coordinates produced by FPS, consumed by KNN.
__device__ float g_centers[BB * SS * 3];

__device__ __forceinline__ ull warp_max_u64(ull k) {
#pragma unroll
    for (int off = 16; off; off >>= 1) {
        ull o = __shfl_xor_sync(0xffffffffu, k, off);
        if (o > k) k = o;
    }
    return k;
}
__device__ __forceinline__ ull warp_min_u64(ull k) {
#pragma unroll
    for (int off = 16; off; off >>= 1) {
        ull o = __shfl_xor_sync(0xffffffffu, k, off);
        if (o < k) k = o;
    }
    return k;
}

// ---- cluster helpers (no mbarriers: barrier.cluster only) ------------------
__device__ __forceinline__ unsigned cta_rank() {
    unsigned r;
    asm("mov.u32 %0, %%cluster_ctarank;" : "=r"(r));
    return r;
}
__device__ __forceinline__ void cluster_sync() {
    // arrive = release (orders prior st.shared::cluster), wait = acquire
    asm volatile("barrier.cluster.arrive.aligned;" ::: "memory");
    asm volatile("barrier.cluster.wait.aligned;" ::: "memory");
}
__device__ __forceinline__ unsigned mapa_u32(unsigned laddr, unsigned rank) {
    unsigned r;
    asm("mapa.shared::cluster.u32 %0, %1, %2;" : "=r"(r) : "r"(laddr), "r"(rank));
    return r;
}
__device__ __forceinline__ void st_remote_u64(unsigned raddr, ull v) {
    asm volatile("st.shared::cluster.u64 [%0], %1;" :: "r"(raddr), "l"(v)
                 : "memory");
}

// ---------------------------------------------------------------------------
// FPS: cluster of 2 CTAs per batch; each CTA owns 4096 points (256 threads
// x 16 register-resident points). Per step, lane 0 of each warp writes its
// 64-bit warp key to local keyAll[p][w] AND to the peer's keyAll[p][8+w]
// (disjoint DSMEM slots), then ONE cluster.sync; every thread reduces the 16
// keys with 4 shfl levels. No __syncthreads, no mbarriers, no phases.
// Parity double-buffer makes the single barrier per step sufficient.
// Argmax tie-break = lowest GLOBAL index (key = dist_bits<<32 | ~idx, max).
// ---------------------------------------------------------------------------
__global__ __launch_bounds__(FPS_T, 1) __cluster_dims__(2, 1, 1)
void fps_kernel(const float* __restrict__ xyz) {
    extern __shared__ float sxyz[];            // 3*NN floats (96 KB)
    __shared__ ull keyAll[2][2 * FW];          // [parity][0..7 own, 8..15 peer]

    const int tid  = threadIdx.x;
    const int lane = tid & 31;
    const int wid  = tid >> 5;
    const unsigned rank = cta_rank();
    const unsigned peer = rank ^ 1u;
    const int b = blockIdx.x >> 1;
    const float* base = xyz + (size_t)b * NN * 3;

    // full-batch coord table (winner-coordinate lookup) in each CTA
    for (int i = tid; i < 3 * NN; i += FPS_T) sxyz[i] = base[i];

    // peer addresses for this warp's remote key slots (both parities)
    const unsigned la0 = (unsigned)__cvta_generic_to_shared(&keyAll[0][FW + wid]);
    const unsigned la1 = (unsigned)__cvta_generic_to_shared(&keyAll[1][FW + wid]);
    const unsigned ra0 = mapa_u32(la0, peer);
    const unsigned ra1 = mapa_u32(la1, peer);

    __syncthreads();                           // sxyz ready (once)

    // register-resident coords (this CTA's half) + running min distance
    const int goff = (int)rank * HALF;
    float px[FPP], py[FPP], pz[FPP], mind[FPP];
#pragma unroll
    for (int k = 0; k < FPP; ++k) {
        int j = goff + tid + (k << 8);         // global point index
        px[k] = sxyz[3 * j + 0];
        py[k] = sxyz[3 * j + 1];
        pz[k] = sxyz[3 * j + 2];
        mind[k] = __int_as_float(0x7f800000);  // +inf
    }

    if (rank == 0 && tid == 0) {               // first selected index is 0
        float* c = g_centers + (size_t)b * SS * 3;
        c[0] = sxyz[0]; c[1] = sxyz[1]; c[2] = sxyz[2];
    }

    int widx = 0;                              // current center (global idx)
    for (int s = 1; s < SS; ++s) {
        const int p = s & 1;
        const float cx = sxyz[3 * widx + 0];
        const float cy = sxyz[3 * widx + 1];
        const float cz = sxyz[3 * widx + 2];

        float best = -__int_as_float(0x7f800000);
#pragma unroll
        for (int k = 0; k < FPP; ++k) {
            float dx = __fadd_rn(px[k], -cx);
            float dy = __fadd_rn(py[k], -cy);
            float dz = __fadd_rn(pz[k], -cz);
            float d = __fadd_rn(__fadd_rn(__fmul_rn(dx, dx), __fmul_rn(dy, dy)),
                                __fmul_rn(dz, dz));
            float m = fminf(mind[k], d);
            mind[k] = m;
            best = fmaxf(best, m);
        }
        // deferred argmax: descending k so the lowest global index wins ties
        int bidx = 0;
#pragma unroll
        for (int k = FPP - 1; k >= 0; --k)
            if (mind[k] == best) bidx = goff + tid + (k << 8);

        ull key = ((ull)__float_as_uint(best) << 32) | (unsigned)(~bidx);
        key = warp_max_u64(key);
        if (lane == 0) {
            keyAll[p][wid] = key;              // own slot, local smem
            st_remote_u64(p ? ra1 : ra0, key); // peer's slot 8+wid (disjoint)
        }

        cluster_sync();                        // the ONLY barrier per step
        // arrive releases our remote stores; wait acquires the peer's.
        // Reuse of keyAll[p] at s+2 is ordered by cluster.sync(s+1).

        ull k2 = keyAll[p][lane & (2 * FW - 1)];
#pragma unroll
        for (int off = FW; off; off >>= 1) {   // 8,4,2,1 -> max of 16
            ull o = __shfl_xor_sync(0xffffffffu, k2, off);
            if (o > k2) k2 = o;
        }
        widx = (int)(~(unsigned)k2);

        if (rank == 0 && tid == 0) {
            float* c = g_centers + ((size_t)b * SS + s) * 3;
            c[0] = sxyz[3 * widx + 0];
            c[1] = sxyz[3 * widx + 1];
            c[2] = sxyz[3 * widx + 2];
        }
    }
    cluster_sync();                            // no CTA exits with peer stores
}

// ---------------------------------------------------------------------------
// KNN: one CTA (256 threads) per center. Distance bits as u32 in smem (index
// = slot). 32 extract-min rounds, ONE barrier per round (double-buffered
// wmin + redundant 8-value reduce); warp-level min cached in a register and
// recomputed only by the warp that owned the extracted point.
// (Byte-identical to the R6 passing version.)
// ---------------------------------------------------------------------------
__global__ __launch_bounds__(KNN_T)
void knn_kernel(const float* __restrict__ xyz, float* __restrict__ dout,
                int write_centers) {
    __shared__ unsigned keys[NN];              // 32 KB
    __shared__ ull wmin[2][KW];
    __shared__ int sel[KK];

    const int cidx = blockIdx.x;               // b * SS + s
    const int b    = cidx >> 11;
    const int tid  = threadIdx.x;
    const int lane = tid & 31;
    const int wid  = tid >> 5;
    const float* base = xyz + (size_t)b * NN * 3;
    const float* c = g_centers + (size_t)cidx * 3;
    const float ncx = -c[0], ncy = -c[1], ncz = -c[2];

    // distances + per-thread cached minimum key
    ull myMin = ~0ull;
#pragma unroll
    for (int r = 0; r < KPT; ++r) {
        int i = tid + (r << 8);
        float dx = __fadd_rn(base[3 * i + 0], ncx);
        float dy = __fadd_rn(base[3 * i + 1], ncy);
        float dz = __fadd_rn(base[3 * i + 2], ncz);
        float d = __fadd_rn(__fadd_rn(__fmul_rn(dx, dx), __fmul_rn(dy, dy)),
                            __fmul_rn(dz, dz));
        unsigned bits = __float_as_uint(d);    // d >= 0 -> monotone as u32
        keys[i] = bits;
        ull v = ((ull)bits << 32) | (unsigned)i;
        if (v < myMin) myMin = v;
    }
    __syncthreads();

    ull wkey = warp_min_u64(myMin);            // cached per-warp minimum

    for (int t = 0; t < KK; ++t) {
        const int p = t & 1;
        if (lane == 0) wmin[p][wid] = wkey;
        __syncthreads();                       // the only barrier per round

        ull m = wmin[p][lane & (KW - 1)];
#pragma unroll
        for (int off = KW / 2; off; off >>= 1) {
            ull o = __shfl_xor_sync(0xffffffffu, m, off);
            if (o < m) m = o;
        }                                      // m = block min (all threads)
        const int opid = (int)(unsigned)m;     // winning point index
        if (tid == 0) sel[t] = opid;

        if (myMin == m) {                      // unique owner thread
            keys[opid] = 0xFFFFFFFFu;          // invalidate
            ull mn = ~0ull;
#pragma unroll
            for (int r = 0; r < KPT; ++r) {
                int i = tid + (r << 8);
                ull v = ((ull)keys[i] << 32) | (unsigned)i;
                if (v < mn) mn = v;
            }
            myMin = mn;
        }
        if (((opid & (KNN_T - 1)) >> 5) == wid)  // only owner warp re-reduces
            wkey = warp_min_u64(myMin);
    }
    __syncthreads();

    // write the 32 re-centered neighbors (order = ascending distance)
    if (tid < KK) {
        int pid = sel[tid];
        float* o = dout + ((size_t)cidx * KK + tid) * 3;
        o[0] = __fadd_rn(base[3 * pid + 0], ncx);
        o[1] = __fadd_rn(base[3 * pid + 1], ncy);
        o[2] = __fadd_rn(base[3 * pid + 2], ncz);
    } else if (write_centers && tid < KK + 3) {
        int comp = tid - KK;
        dout[(size_t)BB * SS * KK * 3 + (size_t)cidx * 3 + comp] = c[comp];
    }
}

// ---------------------------------------------------------------------------

extern "C" void kernel_launch(void* const* d_in, const int* in_sizes, int n_in,
                              void* d_out, int out_size) {
    (void)in_sizes; (void)n_in;
    const float* xyz = (const float*)d_in[0];
    float* out = (float*)d_out;

    const int full = BB * SS * KK * 3 + BB * SS * 3;
    int write_centers = (out_size >= full) ? 1 : 0;

    const int fps_smem = 3 * NN * (int)sizeof(float);  // 96 KB dynamic
    cudaFuncSetAttribute(fps_kernel,
                         cudaFuncAttributeMaxDynamicSharedMemorySize, fps_smem);

    fps_kernel<<<BB * 2, FPS_T, fps_smem>>>(xyz);
    knn_kernel<<<BB * SS, KNN_T>>>(xyz, out, write_centers);
}

// round 11
// speedup vs baseline: 1.1084x; 1.1084x over previous
#include <cuda_runtime.h>

// Grouper: FPS (B=8, N=8192 -> S=2048) + KNN(K=32) grouping.
// Output layout: [neighborhood (B,S,K,3) | centers (B,S,3)] flattened.
//
// All distance math is scalar __fadd_rn/__fmul_rn (no FMA contraction, no
// packed f32x2 — R5 showed the packed path is NOT bit-identical), in the
// reference's ((dx^2+dy^2)+dz^2) evaluation order. All selections use 64-bit
// keys reproducing JAX first-occurrence (lowest-index) tie-breaking.
//
// R9 lesson: per-step cluster sync (~600 cyc) loses to single-CTA FPS; FPS
// here is the R6-proven single-CTA version. KNN rewritten as threshold
// select (register keys + 10-step prefix binary search) + small exact sort.
// R10 run died to an infra-level container failure (no hang mode exists in
// this source: no spin loops, uniform barriers, fixed trip counts, guarded
// stores) — resubmitting unchanged to get a clean measurement.

#define BB 8
#define NN 8192
#define SS 2048
#define KK 32

#define FPS_T 512
#define FPP   16              // points per thread (NN / FPS_T)
#define FW    (FPS_T / 32)    // 16 warps

#define KNN_T 256
#define KW    (KNN_T / 32)    // 8 warps
#define KPT   32              // points per thread (NN / KNN_T)
#define CAP   1024            // candidate buffer (8 KB)
#define KR    8               // register candidates per lane (covers C<=256)

typedef unsigned long long ull;

// Scratch: centers coordinates produced by FPS, consumed by KNN.
__device__ float g_centers[BB * SS * 3];

__device__ __forceinline__ ull warp_max_u64(ull k) {
#pragma unroll
    for (int off = 16; off; off >>= 1) {
        ull o = __shfl_xor_sync(0xffffffffu, k, off);
        if (o > k) k = o;
    }
    return k;
}
__device__ __forceinline__ ull warp_min_u64(ull k) {
#pragma unroll
    for (int off = 16; off; off >>= 1) {
        ull o = __shfl_xor_sync(0xffffffffu, k, off);
        if (o < k) k = o;
    }
    return k;
}

// ---------------------------------------------------------------------------
// FPS: one CTA per batch, 512 threads x 16 points in registers.
// (Byte-identical to the R6 passing version: 1520 us measured.)
// ---------------------------------------------------------------------------
__global__ __launch_bounds__(FPS_T, 1)
void fps_kernel(const float* __restrict__ xyz) {
    extern __shared__ float sxyz[];            // 3*NN floats (96 KB)
    __shared__ ull warpKey[2][FW];

    const int b    = blockIdx.x;
    const int tid  = threadIdx.x;
    const int lane = tid & 31;
    const int wid  = tid >> 5;
    const float* base = xyz + (size_t)b * NN * 3;

    for (int i = tid; i < 3 * NN; i += FPS_T) sxyz[i] = base[i];
    __syncthreads();

    float px[FPP], py[FPP], pz[FPP], mind[FPP];
#pragma unroll
    for (int k = 0; k < FPP; ++k) {
        int j = tid + k * FPS_T;
        px[k] = sxyz[3 * j + 0];
        py[k] = sxyz[3 * j + 1];
        pz[k] = sxyz[3 * j + 2];
        mind[k] = __int_as_float(0x7f800000);  // +inf
    }

    if (tid == 0) {                            // first selected index is 0
        float* c = g_centers + (size_t)b * SS * 3;
        c[0] = sxyz[0]; c[1] = sxyz[1]; c[2] = sxyz[2];
    }

    int widx = 0;                              // current center index (uniform)
    for (int s = 1; s < SS; ++s) {
        const int p = s & 1;
        const float cx = sxyz[3 * widx + 0];
        const float cy = sxyz[3 * widx + 1];
        const float cz = sxyz[3 * widx + 2];

        float best = -__int_as_float(0x7f800000);
#pragma unroll
        for (int k = 0; k < FPP; ++k) {
            float dx = __fadd_rn(px[k], -cx);
            float dy = __fadd_rn(py[k], -cy);
            float dz = __fadd_rn(pz[k], -cz);
            float d = __fadd_rn(__fadd_rn(__fmul_rn(dx, dx), __fmul_rn(dy, dy)),
                                __fmul_rn(dz, dz));
            float m = fminf(mind[k], d);
            mind[k] = m;
            best = fmaxf(best, m);
        }
        // deferred argmax: descending k so the lowest index wins ties
        int bidx = 0;
#pragma unroll
        for (int k = FPP - 1; k >= 0; --k)
            if (mind[k] == best) bidx = tid + (k << 9);

        ull key = ((ull)__float_as_uint(best) << 32) | (unsigned)(~bidx);
        key = warp_max_u64(key);
        if (lane == 0) warpKey[p][wid] = key;
        __syncthreads();                       // the only barrier per step

        ull k2 = warpKey[p][lane & (FW - 1)];
#pragma unroll
        for (int off = FW / 2; off; off >>= 1) {
            ull o = __shfl_xor_sync(0xffffffffu, k2, off);
            if (o > k2) k2 = o;
        }
        widx = (int)(~(unsigned)k2);

        if (tid == 0) {
            float* c = g_centers + ((size_t)b * SS + s) * 3;
            c[0] = sxyz[3 * widx + 0];
            c[1] = sxyz[3 * widx + 1];
            c[2] = sxyz[3 * widx + 2];
        }
    }
}

// ---------------------------------------------------------------------------
// KNN: one CTA (256 threads) per center. Distance bits live in REGISTERS
// (32/thread). 10-iteration binary search on the 10-bit float prefix finds
// the tightest threshold bin containing the 32nd smallest key (prefix
// truncation is monotone on nonneg floats, so top-32 full keys are a subset
// of the gathered set). Candidates (~32..200) gathered to smem; warp 0 does
// 32 exact extract-min rounds over register-held candidates — no block
// barriers in the selection loop. Same 64-bit (bits<<32|idx) key order.
// ---------------------------------------------------------------------------
__global__ __launch_bounds__(KNN_T, 3)
void knn_kernel(const float* __restrict__ xyz, float* __restrict__ dout,
                int write_centers) {
    __shared__ ull cand[CAP];                  // 8 KB
    __shared__ unsigned wcnt[2][KW];
    __shared__ int ccount;
    __shared__ int sel[KK];

    const int cidx = blockIdx.x;               // b * SS + s
    const int b    = cidx >> 11;
    const int tid  = threadIdx.x;
    const int lane = tid & 31;
    const int wid  = tid >> 5;
    const float* base = xyz + (size_t)b * NN * 3;
    const float* c = g_centers + (size_t)cidx * 3;
    const float ncx = -c[0], ncy = -c[1], ncz = -c[2];

    if (tid == 0) ccount = 0;

    unsigned mykeys[KPT];                      // register-resident
#pragma unroll
    for (int r = 0; r < KPT; ++r) {
        int i = tid + (r << 8);
        float dx = __fadd_rn(base[3 * i + 0], ncx);
        float dy = __fadd_rn(base[3 * i + 1], ncy);
        float dz = __fadd_rn(base[3 * i + 2], ncz);
        float d = __fadd_rn(__fadd_rn(__fmul_rn(dx, dx), __fmul_rn(dy, dy)),
                            __fmul_rn(dz, dz));
        mykeys[r] = __float_as_uint(d);        // d >= 0 -> monotone as u32
    }

    // binary search on 10-bit prefix: smallest B with count(<= bin B) >= 32
    unsigned lo = 0, hi = 1023;
    for (int it = 0; it < 10; ++it) {
        unsigned mid = (lo + hi) >> 1;
        unsigned T = (mid << 22) | 0x3FFFFFu;
        unsigned cme = 0;
#pragma unroll
        for (int r = 0; r < KPT; ++r) cme += (mykeys[r] <= T);
        unsigned ws = __reduce_add_sync(0xffffffffu, cme);
        const int p = it & 1;
        if (lane == 0) wcnt[p][wid] = ws;
        __syncthreads();                       // one barrier per iteration
        unsigned tot = 0;
#pragma unroll
        for (int w = 0; w < KW; ++w) tot += wcnt[p][w];
        if (tot >= KK) hi = mid; else lo = mid + 1;
        // wcnt[p] reuse at it+2 ordered by the barrier at it+1
    }
    const unsigned TB = (lo << 22) | 0x3FFFFFu;

    // gather candidates (ccount=0 write is ordered by the search barriers)
#pragma unroll
    for (int r = 0; r < KPT; ++r) {
        if (mykeys[r] <= TB) {
            int pos = atomicAdd(&ccount, 1);
            if (pos < CAP)
                cand[pos] = ((ull)mykeys[r] << 32) | (unsigned)(tid + (r << 8));
        }
    }
    __syncthreads();
    int C = ccount;
    if (C > CAP) C = CAP;                      // CAP overflow: never in practice

    // warp 0: 32 exact extract-min rounds, candidates in registers
    if (wid == 0) {
        ull regs[KR];
#pragma unroll
        for (int j = 0; j < KR; ++j) {
            int i = lane + (j << 5);
            regs[j] = (i < C) ? cand[i] : ~0ull;
        }
        for (int t = 0; t < KK; ++t) {
            ull lmin = ~0ull;
#pragma unroll
            for (int j = 0; j < KR; ++j)
                if (regs[j] < lmin) lmin = regs[j];
            for (int i = (KR << 5) + lane; i < C; i += 32) {  // rare fallback
                ull v = cand[i];
                if (v < lmin) lmin = v;
            }
            ull w = warp_min_u64(lmin);
            if (lane == 0) sel[t] = (int)(unsigned)w;
#pragma unroll
            for (int j = 0; j < KR; ++j)
                if (regs[j] == w) regs[j] = ~0ull;
            for (int i = (KR << 5) + lane; i < C; i += 32)
                if (cand[i] == w) cand[i] = ~0ull;
        }
    }
    __syncthreads();

    // write the 32 re-centered neighbors (order = ascending (dist, idx))
    if (tid < KK) {
        int pid = sel[tid];
        float* o = dout + ((size_t)cidx * KK + tid) * 3;
        o[0] = __fadd_rn(base[3 * pid + 0], ncx);
        o[1] = __fadd_rn(base[3 * pid + 1], ncy);
        o[2] = __fadd_rn(base[3 * pid + 2], ncz);
    } else if (write_centers && tid < KK + 3) {
        int comp = tid - KK;
        dout[(size_t)BB * SS * KK * 3 + (size_t)cidx * 3 + comp] = c[comp];
    }
}

// ---------------------------------------------------------------------------

extern "C" void kernel_launch(void* const* d_in, const int* in_sizes, int n_in,
                              void* d_out, int out_size) {
    (void)in_sizes; (void)n_in;
    const float* xyz = (const float*)d_in[0];
    float* out = (float*)d_out;

    const int full = BB * SS * KK * 3 + BB * SS * 3;
    int write_centers = (out_size >= full) ? 1 : 0;

    const int fps_smem = 3 * NN * (int)sizeof(float);  // 96 KB dynamic
    cudaFuncSetAttribute(fps_kernel,
                         cudaFuncAttributeMaxDynamicSharedMemorySize, fps_smem);

    fps_kernel<<<BB, FPS_T, fps_smem>>>(xyz);
    knn_kernel<<<BB * SS, KNN_T>>>(xyz, out, write_centers);
}

// round 13
// speedup vs baseline: 1.1993x; 1.0820x over previous
#include <cuda_runtime.h>

// Grouper: FPS (B=8, N=8192 -> S=2048) + KNN(K=32) grouping.
// Output layout: [neighborhood (B,S,K,3) | centers (B,S,3)] flattened.
//
// All distance math is scalar __fadd_rn/__fmul_rn (no FMA contraction, no
// packed f32x2 — R5 showed the packed path is NOT bit-identical), in the
// reference's ((dx^2+dy^2)+dz^2) evaluation order. All selections use 64-bit
// keys reproducing JAX first-occurrence (lowest-index) tie-breaking.
//
// R9: per-step cluster sync loses to single-CTA FPS (kept R6 FPS verbatim).
// R11: KNN threshold-select works (588->493) but was reg-capped at occ 36.6%
// with a serial warp-0 extract-min tail. This round: 512 threads x 16 keys
// (occ 50%) + fully parallel rank-based selection (ranks of distinct 64-bit
// keys are unique -> sel[rank]=idx is exactly the ascending top-k order).

#define BB 8
#define NN 8192
#define SS 2048
#define KK 32

#define FPS_T 512
#define FPP   16              // points per thread (NN / FPS_T)
#define FW    (FPS_T / 32)    // 16 warps

#define KNN_T 512
#define KW    (KNN_T / 32)    // 16 warps
#define KPT   16              // points per thread (NN / KNN_T)
#define CAP   1024            // candidate buffer (8 KB)

typedef unsigned long long ull;

// Scratch: centers coordinates produced by FPS, consumed by KNN.
__device__ float g_centers[BB * SS * 3];

__device__ __forceinline__ ull warp_max_u64(ull k) {
#pragma unroll
    for (int off = 16; off; off >>= 1) {
        ull o = __shfl_xor_sync(0xffffffffu, k, off);
        if (o > k) k = o;
    }
    return k;
}

// ---------------------------------------------------------------------------
// FPS: one CTA per batch, 512 threads x 16 points in registers.
// (Byte-identical to the R6/R11 passing version: ~1513 us measured.)
// ---------------------------------------------------------------------------
__global__ __launch_bounds__(FPS_T, 1)
void fps_kernel(const float* __restrict__ xyz) {
    extern __shared__ float sxyz[];            // 3*NN floats (96 KB)
    __shared__ ull warpKey[2][FW];

    const int b    = blockIdx.x;
    const int tid  = threadIdx.x;
    const int lane = tid & 31;
    const int wid  = tid >> 5;
    const float* base = xyz + (size_t)b * NN * 3;

    for (int i = tid; i < 3 * NN; i += FPS_T) sxyz[i] = base[i];
    __syncthreads();

    float px[FPP], py[FPP], pz[FPP], mind[FPP];
#pragma unroll
    for (int k = 0; k < FPP; ++k) {
        int j = tid + k * FPS_T;
        px[k] = sxyz[3 * j + 0];
        py[k] = sxyz[3 * j + 1];
        pz[k] = sxyz[3 * j + 2];
        mind[k] = __int_as_float(0x7f800000);  // +inf
    }

    if (tid == 0) {                            // first selected index is 0
        float* c = g_centers + (size_t)b * SS * 3;
        c[0] = sxyz[0]; c[1] = sxyz[1]; c[2] = sxyz[2];
    }

    int widx = 0;                              // current center index (uniform)
    for (int s = 1; s < SS; ++s) {
        const int p = s & 1;
        const float cx = sxyz[3 * widx + 0];
        const float cy = sxyz[3 * widx + 1];
        const float cz = sxyz[3 * widx + 2];

        float best = -__int_as_float(0x7f800000);
#pragma unroll
        for (int k = 0; k < FPP; ++k) {
            float dx = __fadd_rn(px[k], -cx);
            float dy = __fadd_rn(py[k], -cy);
            float dz = __fadd_rn(pz[k], -cz);
            float d = __fadd_rn(__fadd_rn(__fmul_rn(dx, dx), __fmul_rn(dy, dy)),
                                __fmul_rn(dz, dz));
            float m = fminf(mind[k], d);
            mind[k] = m;
            best = fmaxf(best, m);
        }
        // deferred argmax: descending k so the lowest index wins ties
        int bidx = 0;
#pragma unroll
        for (int k = FPP - 1; k >= 0; --k)
            if (mind[k] == best) bidx = tid + (k << 9);

        ull key = ((ull)__float_as_uint(best) << 32) | (unsigned)(~bidx);
        key = warp_max_u64(key);
        if (lane == 0) warpKey[p][wid] = key;
        __syncthreads();                       // the only barrier per step

        ull k2 = warpKey[p][lane & (FW - 1)];
#pragma unroll
        for (int off = FW / 2; off; off >>= 1) {
            ull o = __shfl_xor_sync(0xffffffffu, k2, off);
            if (o > k2) k2 = o;
        }
        widx = (int)(~(unsigned)k2);

        if (tid == 0) {
            float* c = g_centers + ((size_t)b * SS + s) * 3;
            c[0] = sxyz[3 * widx + 0];
            c[1] = sxyz[3 * widx + 1];
            c[2] = sxyz[3 * widx + 2];
        }
    }
}

// ---------------------------------------------------------------------------
// KNN: one CTA (512 threads) per center, 16 distance keys per thread in
// registers. 10-iteration binary search on the 10-bit float prefix finds the
// tightest threshold containing the 32nd smallest key (prefix truncation is
// monotone on nonneg floats -> true top-32 is a subset of the candidates).
// Candidates gathered to smem; final selection is PARALLEL rank computation:
// keys are distinct, so rank_i = #{key_j < key_i} is unique and sel[rank]=idx
// reproduces the ascending (dist, idx) top-k order exactly.
// ---------------------------------------------------------------------------
__global__ __launch_bounds__(KNN_T, 2)
void knn_kernel(const float* __restrict__ xyz, float* __restrict__ dout,
                int write_centers) {
    __shared__ ull cand[CAP];                  // 8 KB
    __shared__ unsigned wcnt[2][KW];
    __shared__ int ccount;
    __shared__ int sel[KK];

    const int cidx = blockIdx.x;               // b * SS + s
    const int b    = cidx >> 11;
    const int tid  = threadIdx.x;
    const int lane = tid & 31;
    const int wid  = tid >> 5;
    const float* base = xyz + (size_t)b * NN * 3;
    const float* c = g_centers + (size_t)cidx * 3;
    const float ncx = -c[0], ncy = -c[1], ncz = -c[2];

    if (tid == 0) ccount = 0;

    unsigned mykeys[KPT];                      // register-resident
#pragma unroll
    for (int r = 0; r < KPT; ++r) {
        int i = tid + (r << 9);
        float dx = __fadd_rn(base[3 * i + 0], ncx);
        float dy = __fadd_rn(base[3 * i + 1], ncy);
        float dz = __fadd_rn(base[3 * i + 2], ncz);
        float d = __fadd_rn(__fadd_rn(__fmul_rn(dx, dx), __fmul_rn(dy, dy)),
                            __fmul_rn(dz, dz));
        mykeys[r] = __float_as_uint(d);        // d >= 0 -> monotone as u32
    }

    // binary search on 10-bit prefix: smallest B with count(<= bin B) >= 32
    unsigned lo = 0, hi = 1023;
    for (int it = 0; it < 10; ++it) {
        unsigned mid = (lo + hi) >> 1;
        unsigned T = (mid << 22) | 0x3FFFFFu;
        unsigned cme = 0;
#pragma unroll
        for (int r = 0; r < KPT; ++r) cme += (mykeys[r] <= T);
        unsigned ws = __reduce_add_sync(0xffffffffu, cme);
        const int p = it & 1;
        if (lane == 0) wcnt[p][wid] = ws;
        __syncthreads();                       // one barrier per iteration
        unsigned tot = wcnt[p][lane & (KW - 1)];
#pragma unroll
        for (int off = KW / 2; off; off >>= 1)
            tot += __shfl_xor_sync(0xffffffffu, tot, off);
        if (tot >= KK) hi = mid; else lo = mid + 1;
        // wcnt[p] reuse at it+2 ordered by the barrier at it+1
    }
    const unsigned TB = (lo << 22) | 0x3FFFFFu;

    // gather candidates (ccount=0 write is ordered by the search barriers)
#pragma unroll
    for (int r = 0; r < KPT; ++r) {
        if (mykeys[r] <= TB) {
            int pos = atomicAdd(&ccount, 1);
            if (pos < CAP)
                cand[pos] = ((ull)mykeys[r] << 32) | (unsigned)(tid + (r << 9));
        }
    }
    __syncthreads();
    int C = ccount;
    if (C > CAP) C = CAP;                      // CAP overflow: never in practice

    // parallel exact selection: unique ranks of distinct 64-bit keys
    for (int i = tid; i < C; i += KNN_T) {
        ull ki = cand[i];
        int rank = 0;
        for (int j = 0; j < C; ++j)
            rank += (cand[j] < ki);
        if (rank < KK) sel[rank] = (int)(unsigned)ki;
    }
    __syncthreads();

    // write the 32 re-centered neighbors (order = ascending (dist, idx))
    if (tid < KK) {
        int pid = sel[tid];
        float* o = dout + ((size_t)cidx * KK + tid) * 3;
        o[0] = __fadd_rn(base[3 * pid + 0], ncx);
        o[1] = __fadd_rn(base[3 * pid + 1], ncy);
        o[2] = __fadd_rn(base[3 * pid + 2], ncz);
    } else if (write_centers && tid < KK + 3) {
        int comp = tid - KK;
        dout[(size_t)BB * SS * KK * 3 + (size_t)cidx * 3 + comp] = c[comp];
    }
}

// ---------------------------------------------------------------------------

extern "C" void kernel_launch(void* const* d_in, const int* in_sizes, int n_in,
                              void* d_out, int out_size) {
    (void)in_sizes; (void)n_in;
    const float* xyz = (const float*)d_in[0];
    float* out = (float*)d_out;

    const int full = BB * SS * KK * 3 + BB * SS * 3;
    int write_centers = (out_size >= full) ? 1 : 0;

    const int fps_smem = 3 * NN * (int)sizeof(float);  // 96 KB dynamic
    cudaFuncSetAttribute(fps_kernel,
                         cudaFuncAttributeMaxDynamicSharedMemorySize, fps_smem);

    fps_kernel<<<BB, FPS_T, fps_smem>>>(xyz);
    knn_kernel<<<BB * SS, KNN_T>>>(xyz, out, write_centers);
}